// round 14
// baseline (speedup 1.0000x reference)
#include <cuda_runtime.h>
#include <cuda_bf16.h>

// CrossNet: B=500000, D=128, L=4.   out = alpha_L * x0 + beta_L
//   d_l = w_l·x0 ; alpha_{l+1} = alpha_l*(1+d_l) + c_l ; c_l = w_l·beta_l
//
// R14: main kernel identical to R13 (ncu 72.7us, DRAM 79%). Setup kernel
// rewritten: all 8 constant loads (4 bias + 4 weight float4 per lane) are
// front-batched & independent -> one memory round trip instead of 4 serial
// ones, cutting ~3us of serialized graph time the R13 setup launch cost.

#define CN_L  4
#define CN_D  128

__device__ float4 g_beta[32];
__device__ float  g_c[CN_L];

// ---- setup: one warp, all loads front-batched ----
__global__ void crossnet_setup(const float4* __restrict__ w4,
                               const float4* __restrict__ b4)
{
    const int ln = threadIdx.x & 31;

    // 8 independent LDGs, all in flight at once
    float4 bl[CN_L], wl[CN_L];
#pragma unroll
    for (int l = 0; l < CN_L; ++l) bl[l] = b4[l * 32 + ln];
#pragma unroll
    for (int l = 0; l < CN_L; ++l) wl[l] = w4[l * 32 + ln];

    // beta prefix + c partials (pure register work)
    float4 bt = make_float4(0.f, 0.f, 0.f, 0.f);
    float cp[CN_L];
#pragma unroll
    for (int l = 0; l < CN_L; ++l) {
        float p = wl[l].x * bt.x;
        p = fmaf(wl[l].y, bt.y, p);
        p = fmaf(wl[l].z, bt.z, p);
        p = fmaf(wl[l].w, bt.w, p);
        cp[l] = p;
        bt.x += bl[l].x; bt.y += bl[l].y; bt.z += bl[l].z; bt.w += bl[l].w;
    }
    // 4 interleaved butterfly chains
#pragma unroll
    for (int off = 16; off > 0; off >>= 1) {
#pragma unroll
        for (int l = 0; l < CN_L; ++l)
            cp[l] += __shfl_xor_sync(0xffffffffu, cp[l], off);
    }
    if (ln == 0) {
#pragma unroll
        for (int l = 0; l < CN_L; ++l) g_c[l] = cp[l];
    }
    g_beta[ln] = bt;
}

// ---- main kernel (identical to R13) ----
__global__ __launch_bounds__(256, 4) void crossnet_kernel(
    const float4* __restrict__ x,     // inputs  [B,128] as float4 [B,32]
    const float4* __restrict__ w4,    // kernels [L,128] as float4
    float4*       __restrict__ out,
    int B)
{
    __shared__ float4 ws[CN_L * 32];  // weights
    __shared__ float4 sbeta[32];      // beta_L
    __shared__ float  sc[CN_L];       // c_l

    const int tid = threadIdx.x;
    if (tid < 128)       ws[tid]          = w4[tid];
    else if (tid < 160)  sbeta[tid - 128] = g_beta[tid - 128];
    else if (tid < 164)  sc[tid - 160]    = g_c[tid - 160];
    __syncthreads();

    const int warp = (blockIdx.x << 3) + (tid >> 5);
    if (warp * 8 >= B) return;

    const int lane = tid & 31;
    const int sub  = lane >> 3;       // row within 4-row group (0..3)
    const int li   = lane & 7;        // lane within 8-lane row team

    const int baseA = (warp * 8 + sub) * 32 + li;
    const int baseB = baseA + 4 * 32;

    // 8 independent LDG.128 per lane, all front-batched
    float4 xa[4], xb[4];
#pragma unroll
    for (int i = 0; i < 4; ++i) xa[i] = __ldcs(&x[baseA + i * 8]);
#pragma unroll
    for (int i = 0; i < 4; ++i) xb[i] = __ldcs(&x[baseB + i * 8]);

    // partial dots d_l = w_l·x0 over this lane's 16 cols (weights from smem)
    float pa[CN_L], pb[CN_L];
#pragma unroll
    for (int l = 0; l < CN_L; ++l) {
        float qa = 0.f, qb = 0.f;
#pragma unroll
        for (int i = 0; i < 4; ++i) {
            const float4 wv = ws[l * 32 + i * 8 + li];
            qa = fmaf(wv.x, xa[i].x, qa);  qb = fmaf(wv.x, xb[i].x, qb);
            qa = fmaf(wv.y, xa[i].y, qa);  qb = fmaf(wv.y, xb[i].y, qb);
            qa = fmaf(wv.z, xa[i].z, qa);  qb = fmaf(wv.z, xb[i].z, qb);
            qa = fmaf(wv.w, xa[i].w, qa);  qb = fmaf(wv.w, xb[i].w, qb);
        }
        pa[l] = qa; pb[l] = qb;
    }
    // 3-level butterfly within 8-lane teams; each SHFL serves 4 rows
#pragma unroll
    for (int off = 1; off < 8; off <<= 1) {
#pragma unroll
        for (int l = 0; l < CN_L; ++l) {
            pa[l] += __shfl_xor_sync(0xffffffffu, pa[l], off);
            pb[l] += __shfl_xor_sync(0xffffffffu, pb[l], off);
        }
    }

    // scalar alpha recurrences
    float aA = 1.0f, aB = 1.0f;
#pragma unroll
    for (int l = 0; l < CN_L; ++l) {
        const float cl = sc[l];
        aA = fmaf(aA, pa[l], aA + cl);
        aB = fmaf(aB, pb[l], aB + cl);
    }

    // epilogue: out = a * x0 + beta
#pragma unroll
    for (int i = 0; i < 4; ++i) {
        const float4 bt = sbeta[i * 8 + li];
        float4 o;
        o.x = fmaf(xa[i].x, aA, bt.x);
        o.y = fmaf(xa[i].y, aA, bt.y);
        o.z = fmaf(xa[i].z, aA, bt.z);
        o.w = fmaf(xa[i].w, aA, bt.w);
        __stcs(&out[baseA + i * 8], o);
        o.x = fmaf(xb[i].x, aB, bt.x);
        o.y = fmaf(xb[i].y, aB, bt.y);
        o.z = fmaf(xb[i].z, aB, bt.z);
        o.w = fmaf(xb[i].w, aB, bt.w);
        __stcs(&out[baseB + i * 8], o);
    }
}

extern "C" void kernel_launch(void* const* d_in, const int* in_sizes, int n_in,
                              void* d_out, int out_size)
{
    const float* x = (const float*)d_in[0];   // inputs  [B,128]
    const float* w = (const float*)d_in[1];   // kernels [L,128,1]
    const float* b = (const float*)d_in[2];   // biases  [L,128,1]
    float* out = (float*)d_out;

    const int B = in_sizes[0] / CN_D;                       // 500000

    crossnet_setup<<<1, 32>>>(
        reinterpret_cast<const float4*>(w),
        reinterpret_cast<const float4*>(b));

    const int warps = (B + 7) / 8;            // 62500
    const int grid  = (warps + 7) / 8;        // 7813

    crossnet_kernel<<<grid, 256>>>(
        reinterpret_cast<const float4*>(x),
        reinterpret_cast<const float4*>(w),
        reinterpret_cast<float4*>(out), B);
}

// round 15
// speedup vs baseline: 1.0297x; 1.0297x over previous
#include <cuda_runtime.h>
#include <cuda_bf16.h>

// CrossNet: B=500000, D=128, L=4.   out = alpha_L * x0 + beta_L
//   d_l = w_l·x0 ; alpha_{l+1} = alpha_l*(1+d_l) + c_l ; c_l = w_l·beta_l
//
// R15: R13's measured-best body (8-lane row teams, 3 SHFL/row, 8 rows/warp,
// 8 front-batched LDG.128/lane, DRAM 79%) repackaged for minimal harness
// overhead: ONE kernel, 128-thread blocks, grid=15625 (exact, zero tail —
// the grid shape with ~0 harness-vs-ncu gap in R3/R12). The per-block
// beta/c prologue is hidden: warps 1-3 issue their DRAM x-loads before the
// barrier while warp 0 computes beta/c from front-batched L2-hit loads.

#define CN_L  4
#define CN_D  128

__global__ __launch_bounds__(128, 8) void crossnet_kernel(
    const float4* __restrict__ x,     // inputs  [B,128] as float4 [B,32]
    const float4* __restrict__ w4,    // kernels [L,128] as float4
    const float4* __restrict__ b4,    // biases
    float4*       __restrict__ out,
    int B)
{
    __shared__ float4 ws[CN_L * 32];  // weights (global layout mirrored)
    __shared__ float4 sbeta[32];      // beta_L
    __shared__ float  sc[CN_L];       // c_l

    const int tid  = threadIdx.x;
    const int wid  = tid >> 5;                     // warp in block (0..3)
    const int lane = tid & 31;
    const int sub  = lane >> 3;                    // row within group (0..3)
    const int li   = lane & 7;                     // lane within 8-lane team

    const int warp  = (blockIdx.x << 2) + wid;     // 4 warps/block
    const int baseA = (warp * 8 + sub) * 32 + li;  // float4 index, < 16M
    const int baseB = baseA + 4 * 32;

    // stage weights (each of the 128 threads loads exactly one float4)
    ws[tid] = w4[tid];

    float4 xa[4], xb[4];
    if (wid != 0) {
        // warps 1-3: front-batch the 8 DRAM row loads BEFORE the barrier,
        // so warp 0's prologue below hides under this latency.
#pragma unroll
        for (int i = 0; i < 4; ++i) xa[i] = __ldcs(&x[baseA + i * 8]);
#pragma unroll
        for (int i = 0; i < 4; ++i) xb[i] = __ldcs(&x[baseB + i * 8]);
    } else {
        // warp 0: beta_L and c_l with all 8 const loads front-batched
        float4 bl[CN_L], wl[CN_L];
#pragma unroll
        for (int l = 0; l < CN_L; ++l) bl[l] = __ldg(&b4[l * 32 + lane]);
#pragma unroll
        for (int l = 0; l < CN_L; ++l) wl[l] = __ldg(&w4[l * 32 + lane]);

        float4 bt = make_float4(0.f, 0.f, 0.f, 0.f);
        float cp[CN_L];
#pragma unroll
        for (int l = 0; l < CN_L; ++l) {
            float p = wl[l].x * bt.x;
            p = fmaf(wl[l].y, bt.y, p);
            p = fmaf(wl[l].z, bt.z, p);
            p = fmaf(wl[l].w, bt.w, p);
            cp[l] = p;
            bt.x += bl[l].x; bt.y += bl[l].y;
            bt.z += bl[l].z; bt.w += bl[l].w;
        }
#pragma unroll
        for (int off = 16; off > 0; off >>= 1) {
#pragma unroll
            for (int l = 0; l < CN_L; ++l)
                cp[l] += __shfl_xor_sync(0xffffffffu, cp[l], off);
        }
        sbeta[lane] = bt;
        if (lane == 0) {
#pragma unroll
            for (int l = 0; l < CN_L; ++l) sc[l] = cp[l];
        }
        // warp 0's own row loads (after prologue to bound register liveness)
#pragma unroll
        for (int i = 0; i < 4; ++i) xa[i] = __ldcs(&x[baseA + i * 8]);
#pragma unroll
        for (int i = 0; i < 4; ++i) xb[i] = __ldcs(&x[baseB + i * 8]);
    }
    __syncthreads();

    if (warp * 8 >= B) return;   // never taken for B=500000 (exact grid)

    // partial dots d_l = w_l·x0 over this lane's 16 cols (weights from smem)
    float pa[CN_L], pb[CN_L];
#pragma unroll
    for (int l = 0; l < CN_L; ++l) {
        float qa = 0.f, qb = 0.f;
#pragma unroll
        for (int i = 0; i < 4; ++i) {
            const float4 wv = ws[l * 32 + i * 8 + li];
            qa = fmaf(wv.x, xa[i].x, qa);  qb = fmaf(wv.x, xb[i].x, qb);
            qa = fmaf(wv.y, xa[i].y, qa);  qb = fmaf(wv.y, xb[i].y, qb);
            qa = fmaf(wv.z, xa[i].z, qa);  qb = fmaf(wv.z, xb[i].z, qb);
            qa = fmaf(wv.w, xa[i].w, qa);  qb = fmaf(wv.w, xb[i].w, qb);
        }
        pa[l] = qa; pb[l] = qb;
    }
    // 3-level butterfly within 8-lane teams; each SHFL serves 4 rows
#pragma unroll
    for (int off = 1; off < 8; off <<= 1) {
#pragma unroll
        for (int l = 0; l < CN_L; ++l) {
            pa[l] += __shfl_xor_sync(0xffffffffu, pa[l], off);
            pb[l] += __shfl_xor_sync(0xffffffffu, pb[l], off);
        }
    }

    // scalar alpha recurrences
    float aA = 1.0f, aB = 1.0f;
#pragma unroll
    for (int l = 0; l < CN_L; ++l) {
        const float cl = sc[l];
        aA = fmaf(aA, pa[l], aA + cl);
        aB = fmaf(aB, pb[l], aB + cl);
    }

    // epilogue: out = a * x0 + beta
#pragma unroll
    for (int i = 0; i < 4; ++i) {
        const float4 bt = sbeta[i * 8 + li];
        float4 o;
        o.x = fmaf(xa[i].x, aA, bt.x);
        o.y = fmaf(xa[i].y, aA, bt.y);
        o.z = fmaf(xa[i].z, aA, bt.z);
        o.w = fmaf(xa[i].w, aA, bt.w);
        __stcs(&out[baseA + i * 8], o);
        o.x = fmaf(xb[i].x, aB, bt.x);
        o.y = fmaf(xb[i].y, aB, bt.y);
        o.z = fmaf(xb[i].z, aB, bt.z);
        o.w = fmaf(xb[i].w, aB, bt.w);
        __stcs(&out[baseB + i * 8], o);
    }
}

extern "C" void kernel_launch(void* const* d_in, const int* in_sizes, int n_in,
                              void* d_out, int out_size)
{
    const float* x = (const float*)d_in[0];   // inputs  [B,128]
    const float* w = (const float*)d_in[1];   // kernels [L,128,1]
    const float* b = (const float*)d_in[2];   // biases  [L,128,1]
    float* out = (float*)d_out;

    const int B = in_sizes[0] / CN_D;          // 500000
    const int warps = (B + 7) / 8;             // 62500 (exact)
    const int grid  = (warps + 3) / 4;         // 15625 (exact, 4 warps/block)

    crossnet_kernel<<<grid, 128>>>(
        reinterpret_cast<const float4*>(x),
        reinterpret_cast<const float4*>(w),
        reinterpret_cast<const float4*>(b),
        reinterpret_cast<float4*>(out), B);
}